// round 17
// baseline (speedup 1.0000x reference)
#include <cuda_runtime.h>
#include <cuda_bf16.h>
#include <mma.h>

#define NN 100000
#define EE 1200000
#define GG 128
#define OUTC 320        // 64*(4+1)
#define ROWS 64         // rows per GEMM tile
#define GT 128          // threads per GEMM block
#define TPB 2           // tiles per persistent GEMM block
#define GBP 782         // GEMM grid: 782*2 = 1564 tiles >= 1563
#define NB 98           // scan blocks = ceil(NN/1024)
#define GA 3125         // gather grid: NN*8/256

// dynamic smem layout (bytes)
#define OFF_ZS   0                  // float Zs[64][68]  = 17408
#define OFF_SC   17408              // float sc[64]
#define OFF_SH   17664              // float sh[64]
#define OFF_SB   17920              // int   sb[64]
#define OFF_WHI  18176              // bf16 Whi[64][64]  = 8192
#define OFF_WLO  26368              // bf16 Wlo[64][64]  = 8192
#define OFF_ZB   34560              // bf16 Zb[64][72]   = 9216
#define SMEM_G   43776

typedef unsigned long long u64;
typedef unsigned int u32;
using namespace nvcuda;

// ---------------- scratch (static __device__, no allocation) ----------------
__device__ __align__(128) __nv_bfloat16 g_u[NN * 64];    // u = h @ W1_next (bf16)
__device__ __align__(128) __nv_bfloat16 g_z1b[NN * 64];  // z1 (bf16)
__device__ int   g_esrc[EE];
__device__ int   g_rowptr[NN + 1];
__device__ int   g_cursor[NN];
__device__ int   g_deg[NN];
__device__ int   g_bsum[NB];
__device__ float g_pool[GG * OUTC];
__device__ int   g_cnt[GG];
__device__ float g_bnsum[4 * 64];
__device__ float g_bnsq[4 * 64];

__device__ __forceinline__ float bf_lo(u32 a) { return __uint_as_float(a << 16); }
__device__ __forceinline__ float bf_hi(u32 a) { return __uint_as_float(a & 0xFFFF0000u); }

// ---------------- one kernel clears all small scratch ----------------
__global__ void clear_kernel() {
    int i = blockIdx.x * 256 + threadIdx.x;
    if (i < GG * OUTC) g_pool[i] = 0.f;
    if (i < GG) g_cnt[i] = 0;
    if (i < NN) g_deg[i] = 0;
    if (i < 4 * 64) { g_bnsum[i] = 0.f; g_bnsq[i] = 0.f; }
}

// ---------------- fused: per-graph node counts + in-degree histogram ----------
__global__ void count_deg_kernel(const int* __restrict__ batch,
                                 const int* __restrict__ ei) {
    int i = blockIdx.x * 256 + threadIdx.x;
    if (i < NN) atomicAdd(&g_cnt[batch[i]], 1);
    if (i < EE) atomicAdd(&g_deg[ei[EE + i]], 1);
}

// ---------------- CSR build ----------------
__global__ void scan1_kernel() {
    __shared__ int s[1024];
    int t = threadIdx.x;
    int i = blockIdx.x * 1024 + t;
    int x = (i < NN) ? g_deg[i] : 0;
    s[t] = x;
    __syncthreads();
#pragma unroll
    for (int off = 1; off < 1024; off <<= 1) {
        int v = (t >= off) ? s[t - off] : 0;
        __syncthreads();
        s[t] += v;
        __syncthreads();
    }
    if (i < NN) g_rowptr[i] = s[t] - x;      // exclusive, partial
    if (t == 1023) g_bsum[blockIdx.x] = s[1023];
}

__global__ void scan23_kernel() {
    __shared__ int sm[128];
    int t = threadIdx.x;
    int b = blockIdx.x;
    if (t < 128) sm[t] = (t < b && t < NB) ? g_bsum[t] : 0;
    __syncthreads();
#pragma unroll
    for (int off = 64; off >= 1; off >>= 1) {
        if (t < off) sm[t] += sm[t + off];
        __syncthreads();
    }
    int prefix = sm[0];
    int i = b * 1024 + t;
    if (i < NN) {
        int v = g_rowptr[i] + prefix;
        g_rowptr[i] = v;
        g_cursor[i] = v;
    }
    if (i == 0) g_rowptr[NN] = EE;
}

__global__ void fill_kernel(const int* __restrict__ ei) {
    int e = blockIdx.x * 256 + threadIdx.x;
    if (e < EE) {
        int dst = ei[EE + e];
        int pos = atomicAdd(&g_cursor[dst], 1);
        g_esrc[pos] = ei[e];
    }
}

// ---------------- bf16 octet accumulate ----------------
__device__ __forceinline__ void acc8(float4& v0, float4& v1, uint4 a) {
    v0.x += bf_lo(a.x); v0.y += bf_hi(a.x);
    v0.z += bf_lo(a.y); v0.w += bf_hi(a.y);
    v1.x += bf_lo(a.z); v1.y += bf_hi(a.z);
    v1.z += bf_lo(a.w); v1.w += bf_hi(a.w);
}

// ---------------- gather: z1[n] = u[n] + sum_{s in N(n)} u[s] + b1, + BN stats
__global__ void gather_kernel(const float* __restrict__ b1, int layer) {
    __shared__ float red[8][8][16];   // 8 warps per 256-thread block
    int t = threadIdx.x;
    int idx = blockIdx.x * 256 + t;       // grid covers NN*8 exactly
    int n = idx >> 3, c = idx & 7;
    int w = t >> 5, lane = t & 31;
    int beg = g_rowptr[n], end = g_rowptr[n + 1];
    const uint4* ub = (const uint4*)g_u;

    float4 v0 = *(const float4*)(b1 + c * 8);       // bias
    float4 v1 = *(const float4*)(b1 + c * 8 + 4);
    acc8(v0, v1, ub[(size_t)n * 8 + c]);            // self term
    int p = beg;
    for (; p + 4 <= end; p += 4) {
        int s0 = g_esrc[p];
        int s1 = g_esrc[p + 1];
        int s2 = g_esrc[p + 2];
        int s3 = g_esrc[p + 3];
        uint4 a0 = ub[(size_t)s0 * 8 + c];
        uint4 a1 = ub[(size_t)s1 * 8 + c];
        uint4 a2 = ub[(size_t)s2 * 8 + c];
        uint4 a3 = ub[(size_t)s3 * 8 + c];
        acc8(v0, v1, a0);
        acc8(v0, v1, a1);
        acc8(v0, v1, a2);
        acc8(v0, v1, a3);
    }
    for (; p < end; p++) acc8(v0, v1, ub[(size_t)g_esrc[p] * 8 + c]);

    // store z1 in bf16 (stats below stay fp32-exact)
    {
        __nv_bfloat162 z0 = __float22bfloat162_rn(make_float2(v0.x, v0.y));
        __nv_bfloat162 z1 = __float22bfloat162_rn(make_float2(v0.z, v0.w));
        __nv_bfloat162 z2 = __float22bfloat162_rn(make_float2(v1.x, v1.y));
        __nv_bfloat162 z3 = __float22bfloat162_rn(make_float2(v1.z, v1.w));
        uint4 uo;
        uo.x = *(u32*)&z0; uo.y = *(u32*)&z1;
        uo.z = *(u32*)&z2; uo.w = *(u32*)&z3;
        *(uint4*)(g_z1b + (size_t)n * 64 + c * 8) = uo;
    }

    float st[16] = { v0.x, v0.y, v0.z, v0.w, v1.x, v1.y, v1.z, v1.w,
                     v0.x * v0.x, v0.y * v0.y, v0.z * v0.z, v0.w * v0.w,
                     v1.x * v1.x, v1.y * v1.y, v1.z * v1.z, v1.w * v1.w };
#pragma unroll
    for (int k = 0; k < 16; k++) {
        st[k] += __shfl_xor_sync(0xFFFFFFFFu, st[k], 8);
        st[k] += __shfl_xor_sync(0xFFFFFFFFu, st[k], 16);
    }
    if (lane < 8) {
#pragma unroll
        for (int k = 0; k < 16; k++) red[w][lane][k] = st[k];
    }
    __syncthreads();
    if (t < 128) {
        int which = t >> 6;            // 0 = sum, 1 = sumsq
        int col = t & 63;
        int cc = col >> 3, j = col & 7;
        float r = 0.f;
#pragma unroll
        for (int ww = 0; ww < 8; ww++) r += red[ww][cc][which * 8 + j];
        if (which == 0) atomicAdd(&g_bnsum[layer * 64 + col], r);
        else            atomicAdd(&g_bnsq[layer * 64 + col], r);
    }
}

// ---------------- fused layer kernel (persistent, 2 tiles/block, HMMA) -------
// BN=true:  m = relu(bn(z1 bf16)); h = m @ W2 + b2; pool h; if NEXT: u = h @ Wn
// BN=false: h = x @ W_emb + b_emb; pool h; u = h @ W1[0] (embedding)
// GEMM cores run on tensor cores: bf16 activations, split-precision weights
// (W = Whi + Wlo, two HMMA passes into one fp32 accumulator).
template <bool BN, bool NEXT>
__global__ __launch_bounds__(GT, 5) void fused_kernel(const float* __restrict__ in,
                             const float* __restrict__ W, const float* __restrict__ b,
                             const float* __restrict__ Wn,
                             const float* __restrict__ gamma, const float* __restrict__ beta,
                             const int* __restrict__ batch, int pool_off, int layer) {
    extern __shared__ char smc[];
    float* Zs = (float*)(smc + OFF_ZS);          // [64][68] fp32
    float* sc = (float*)(smc + OFF_SC);
    float* sh = (float*)(smc + OFF_SH);
    int*   sb = (int*)(smc + OFF_SB);
    __nv_bfloat16* Whi = (__nv_bfloat16*)(smc + OFF_WHI);  // [64][64]
    __nv_bfloat16* Wlo = (__nv_bfloat16*)(smc + OFF_WLO);  // [64][64]
    __nv_bfloat16* Zb  = (__nv_bfloat16*)(smc + OFF_ZB);   // [64][72]

    int t = threadIdx.x;
    int w = t >> 5, lane = t & 31;

    if (t < 64 && BN) {
        float mu = g_bnsum[layer * 64 + t] * (1.f / NN);
        float var = g_bnsq[layer * 64 + t] * (1.f / NN) - mu * mu;
        float rs = rsqrtf(var + 1e-5f);
        float s = gamma[t] * rs;
        sc[t] = s;
        sh[t] = beta[t] - mu * s;
    }

    wmma::fragment<wmma::matrix_a, 16, 16, 16, __nv_bfloat16, wmma::row_major> af;
    wmma::fragment<wmma::matrix_b, 16, 16, 16, __nv_bfloat16, wmma::row_major> bfr;
    wmma::fragment<wmma::accumulator, 16, 16, 16, float> acc[4];

    for (int tile = 0; tile < TPB; tile++) {
        int row0 = (blockIdx.x * TPB + tile) * ROWS;
        __syncthreads();   // sync0: prior tile done; sc/sh visible (tile 0)

        if (t < 64) {
            int gr = row0 + t;
            sb[t] = (gr < NN) ? batch[gr] : -1;
        }
        // W -> Whi/Wlo split (32 elements/thread)
#pragma unroll 8
        for (int i = 0; i < 32; i++) {
            int idx = t + i * GT;
            float wv = W[idx];
            __nv_bfloat16 hi = __float2bfloat16(wv);
            Whi[idx] = hi;
            Wlo[idx] = __float2bfloat16(wv - __bfloat162float(hi));
        }
        // input -> Zb (bf16, activated): 64 rows x 8 chunks, 4 iters
#pragma unroll
        for (int i = 0; i < 4; i++) {
            int e = t + i * GT;
            int r = e >> 3, cb = e & 7;
            int gr = row0 + r;
            uint4 uo = make_uint4(0, 0, 0, 0);
            if (gr < NN) {
                if (BN) {
                    uint4 a = *(const uint4*)(g_z1b + (size_t)gr * 64 + cb * 8);
                    int k = cb * 8;
                    float f0 = fmaxf(bf_lo(a.x) * sc[k]     + sh[k],     0.f);
                    float f1 = fmaxf(bf_hi(a.x) * sc[k + 1] + sh[k + 1], 0.f);
                    float f2 = fmaxf(bf_lo(a.y) * sc[k + 2] + sh[k + 2], 0.f);
                    float f3 = fmaxf(bf_hi(a.y) * sc[k + 3] + sh[k + 3], 0.f);
                    float f4 = fmaxf(bf_lo(a.z) * sc[k + 4] + sh[k + 4], 0.f);
                    float f5 = fmaxf(bf_hi(a.z) * sc[k + 5] + sh[k + 5], 0.f);
                    float f6 = fmaxf(bf_lo(a.w) * sc[k + 6] + sh[k + 6], 0.f);
                    float f7 = fmaxf(bf_hi(a.w) * sc[k + 7] + sh[k + 7], 0.f);
                    __nv_bfloat162 h0 = __float22bfloat162_rn(make_float2(f0, f1));
                    __nv_bfloat162 h1 = __float22bfloat162_rn(make_float2(f2, f3));
                    __nv_bfloat162 h2 = __float22bfloat162_rn(make_float2(f4, f5));
                    __nv_bfloat162 h3 = __float22bfloat162_rn(make_float2(f6, f7));
                    uo.x = *(u32*)&h0; uo.y = *(u32*)&h1;
                    uo.z = *(u32*)&h2; uo.w = *(u32*)&h3;
                } else {
                    float4 x0 = ((const float4*)in)[(size_t)gr * 16 + cb * 2];
                    float4 x1 = ((const float4*)in)[(size_t)gr * 16 + cb * 2 + 1];
                    __nv_bfloat162 h0 = __float22bfloat162_rn(make_float2(x0.x, x0.y));
                    __nv_bfloat162 h1 = __float22bfloat162_rn(make_float2(x0.z, x0.w));
                    __nv_bfloat162 h2 = __float22bfloat162_rn(make_float2(x1.x, x1.y));
                    __nv_bfloat162 h3 = __float22bfloat162_rn(make_float2(x1.z, x1.w));
                    uo.x = *(u32*)&h0; uo.y = *(u32*)&h1;
                    uo.z = *(u32*)&h2; uo.w = *(u32*)&h3;
                }
            }
            *(uint4*)(Zb + r * 72 + cb * 8) = uo;
        }
        __syncthreads();   // sync1: Zb + Whi/Wlo ready

        // ---- core 1: h = Zb @ (Whi + Wlo)  (bias added later) ----
#pragma unroll
        for (int j = 0; j < 4; j++) wmma::fill_fragment(acc[j], 0.f);
#pragma unroll
        for (int kk = 0; kk < 4; kk++) {
            wmma::load_matrix_sync(af, Zb + w * 16 * 72 + kk * 16, 72);
#pragma unroll
            for (int j = 0; j < 4; j++) {
                wmma::load_matrix_sync(bfr, Whi + kk * 16 * 64 + j * 16, 64);
                wmma::mma_sync(acc[j], af, bfr, acc[j]);
                wmma::load_matrix_sync(bfr, Wlo + kk * 16 * 64 + j * 16, 64);
                wmma::mma_sync(acc[j], af, bfr, acc[j]);
            }
        }
#pragma unroll
        for (int j = 0; j < 4; j++)
            wmma::store_matrix_sync(Zs + w * 16 * 68 + j * 16, acc[j], 68,
                                    wmma::mem_row_major);
        __syncthreads();   // sync2: Zs = h (pre-bias), Zb/W free

        // bias add (+ h->bf16 into Zb for core 2); load Wn split
#pragma unroll 8
        for (int i = 0; i < 32; i++) {
            int idx = t + i * GT;
            int r = idx >> 6, c = idx & 63;
            float v = Zs[r * 68 + c] + b[c];
            Zs[r * 68 + c] = v;
            if (NEXT) Zb[r * 72 + c] = __float2bfloat16(v);
        }
        if (NEXT) {
#pragma unroll 8
            for (int i = 0; i < 32; i++) {
                int idx = t + i * GT;
                float wv = Wn[idx];
                __nv_bfloat16 hi = __float2bfloat16(wv);
                Whi[idx] = hi;
                Wlo[idx] = __float2bfloat16(wv - __bfloat162float(hi));
            }
        }
        __syncthreads();   // sync3: Zs = h final, Zb = h bf16, W = Wn split

        // core 2 MMA compute (regs only) runs alongside the pool epilogue
        if (NEXT) {
#pragma unroll
            for (int j = 0; j < 4; j++) wmma::fill_fragment(acc[j], 0.f);
#pragma unroll
            for (int kk = 0; kk < 4; kk++) {
                wmma::load_matrix_sync(af, Zb + w * 16 * 72 + kk * 16, 72);
#pragma unroll
                for (int j = 0; j < 4; j++) {
                    wmma::load_matrix_sync(bfr, Whi + kk * 16 * 64 + j * 16, 64);
                    wmma::mma_sync(acc[j], af, bfr, acc[j]);
                    wmma::load_matrix_sync(bfr, Wlo + kk * 16 * 64 + j * 16, 64);
                    wmma::mma_sync(acc[j], af, bfr, acc[j]);
                }
            }
        }

        // segmented mean-pool over h (Zs); both halves active, 32 rows each
        {
            int col = t & 63, half = t >> 6;
            int r0 = half * 32, r1 = r0 + 32;
            float s = 0.f;
            int cur = sb[r0];
            for (int r = r0; r < r1; r++) {
                int g2 = sb[r];
                if (g2 != cur) {
                    if (cur >= 0) atomicAdd(&g_pool[cur * OUTC + pool_off + col], s);
                    s = 0.f;
                    cur = g2;
                }
                s += Zs[r * 68 + col];
            }
            if (cur >= 0) atomicAdd(&g_pool[cur * OUTC + pool_off + col], s);
        }
        __syncthreads();   // sync4: pool done; Zs free for core-2 output

        if (NEXT) {
#pragma unroll
            for (int j = 0; j < 4; j++)
                wmma::store_matrix_sync(Zs + w * 16 * 68 + j * 16, acc[j], 68,
                                        wmma::mem_row_major);
            // warp-local: write u (bf16) to global from own strip
#pragma unroll
            for (int i = 0; i < 4; i++) {
                int e = lane + i * 32;
                int r = e >> 3, cb = e & 7;
                int gr = row0 + w * 16 + r;
                if (gr < NN) {
                    const float* src = Zs + (w * 16 + r) * 68 + cb * 8;
                    __nv_bfloat162 h0 = __float22bfloat162_rn(make_float2(src[0], src[1]));
                    __nv_bfloat162 h1 = __float22bfloat162_rn(make_float2(src[2], src[3]));
                    __nv_bfloat162 h2 = __float22bfloat162_rn(make_float2(src[4], src[5]));
                    __nv_bfloat162 h3 = __float22bfloat162_rn(make_float2(src[6], src[7]));
                    uint4 uo;
                    uo.x = *(u32*)&h0; uo.y = *(u32*)&h1;
                    uo.z = *(u32*)&h2; uo.w = *(u32*)&h3;
                    *(uint4*)(g_u + (size_t)gr * 64 + cb * 8) = uo;
                }
            }
        }
    }
}

__global__ void finalize_kernel(float* __restrict__ out) {
    int i = blockIdx.x * 256 + threadIdx.x;
    if (i < GG * OUTC) {
        int g = i / OUTC;
        float c = (float)max(g_cnt[g], 1);
        out[i] = g_pool[i] / c;
    }
}

// ---------------- host ----------------
extern "C" void kernel_launch(void* const* d_in, const int* in_sizes, int n_in,
                              void* d_out, int out_size) {
    const float* x     = (const float*)d_in[0];
    const int*   ei    = (const int*)d_in[1];
    const int*   batch = (const int*)d_in[2];
    const float* W_emb = (const float*)d_in[3];
    const float* b_emb = (const float*)d_in[4];
    const float* W1    = (const float*)d_in[5];
    const float* b1    = (const float*)d_in[6];
    const float* gamma = (const float*)d_in[7];
    const float* beta  = (const float*)d_in[8];
    const float* W2    = (const float*)d_in[9];
    const float* b2    = (const float*)d_in[10];
    float* out = (float*)d_out;

    // persistent side-stream + events (host resources only; created once)
    static cudaStream_t sB = nullptr;
    static cudaEvent_t evFork = nullptr, evJoin = nullptr;
    if (sB == nullptr) {
        cudaStreamCreateWithFlags(&sB, cudaStreamNonBlocking);
        cudaEventCreateWithFlags(&evFork, cudaEventDisableTiming);
        cudaEventCreateWithFlags(&evJoin, cudaEventDisableTiming);
    }

    cudaFuncSetAttribute(fused_kernel<false, true>,
                         cudaFuncAttributeMaxDynamicSharedMemorySize, SMEM_G);
    cudaFuncSetAttribute(fused_kernel<true, true>,
                         cudaFuncAttributeMaxDynamicSharedMemorySize, SMEM_G);
    cudaFuncSetAttribute(fused_kernel<true, false>,
                         cudaFuncAttributeMaxDynamicSharedMemorySize, SMEM_G);

    clear_kernel<<<(NN + 255) / 256, 256>>>();

    // fork: embedding (x@W_emb+b_emb, pool, u0 = emb@W1[0]) on side stream
    cudaEventRecord(evFork, 0);
    cudaStreamWaitEvent(sB, evFork, 0);
    fused_kernel<false, true><<<GBP, GT, SMEM_G, sB>>>(x, W_emb, b_emb, W1,
                                                       nullptr, nullptr, batch, 0, 0);
    cudaEventRecord(evJoin, sB);

    // CSR build on the main stream, concurrent with the embedding
    count_deg_kernel<<<(EE + 255) / 256, 256>>>(batch, ei);
    scan1_kernel<<<NB, 1024>>>();
    scan23_kernel<<<NB, 1024>>>();
    fill_kernel<<<(EE + 255) / 256, 256>>>(ei);

    // join: layer loop needs both g_u (embedding) and g_esrc (CSR)
    cudaStreamWaitEvent(0, evJoin, 0);

    for (int l = 0; l < 4; l++) {
        gather_kernel<<<GA, 256>>>(b1 + l * 64, l);
        if (l < 3)
            fused_kernel<true, true><<<GBP, GT, SMEM_G>>>(nullptr,
                W2 + l * 4096, b2 + l * 64, W1 + (l + 1) * 4096,
                gamma + l * 64, beta + l * 64, batch, (l + 1) * 64, l);
        else
            fused_kernel<true, false><<<GBP, GT, SMEM_G>>>(nullptr,
                W2 + l * 4096, b2 + l * 64, nullptr,
                gamma + l * 64, beta + l * 64, batch, (l + 1) * 64, l);
    }

    finalize_kernel<<<(GG * OUTC + 255) / 256, 256>>>(out);
}